// round 1
// baseline (speedup 1.0000x reference)
#include <cuda_runtime.h>

// Problem constants
#define TD     64          // time dim
#define MODES  16
#define MRI    32          // 2*MODES (re/im interleaved rows)
#define CIN    64
#define COUT   64
#define PD     16384       // N*D = 1024*16 pixels
#define SCOL   1048576     // PD*64  (columns per time row, also per-mri row length)

// Scratch (module-load allocated, no cudaMalloc)
__device__ float g_Xft[33554432];   // [mri][p*64+c]  = 32 * 1048576 floats (128 MB)
__device__ float g_Y  [33554432];   // [mri][p*64+o]

#define TWO_PI_OVER_64 0.09817477042468103870f

// ---------- packed f32x2 helpers ----------
__device__ __forceinline__ unsigned long long pack2(float a, float b) {
    unsigned long long r;
    asm("mov.b64 %0, {%1, %2};" : "=l"(r) : "f"(a), "f"(b));
    return r;
}
__device__ __forceinline__ void unpack2(unsigned long long v, float &lo, float &hi) {
    asm("mov.b64 {%0, %1}, %2;" : "=f"(lo), "=f"(hi) : "l"(v));
}
__device__ __forceinline__ void fma2(unsigned long long &d, unsigned long long a, unsigned long long b) {
    asm("fma.rn.f32x2 %0, %1, %2, %0;" : "+l"(d) : "l"(a), "l"(b));
}

// =====================================================================
// Kernel 1: truncated real DFT along t.
//   Xft[2m  ][p][c] =  sum_t x[t][p][c] * cos(2*pi*m*t/64)
//   Xft[2m+1][p][c] = -sum_t x[t][p][c] * sin(2*pi*m*t/64)
// Each thread owns 2 adjacent columns (f32x2). 2048 blocks * 256 thr.
// =====================================================================
__global__ void __launch_bounds__(256) k1_rfft(const float* __restrict__ x) {
    __shared__ unsigned long long F2[MRI * TD];   // packed (f,f), [mri][t]
    const int tid = threadIdx.x;
    for (int idx = tid; idx < MRI * TD; idx += 256) {
        int mri = idx >> 6;
        int t   = idx & 63;
        int m   = mri >> 1;
        float ang = (float)((m * t) & 63) * TWO_PI_OVER_64;
        float s, c;
        sincosf(ang, &s, &c);
        float v = (mri & 1) ? -s : c;
        F2[idx] = pack2(v, v);
    }
    __syncthreads();

    const long col = ((long)blockIdx.x * 256 + tid) * 2;
    unsigned long long acc[MRI];
#pragma unroll
    for (int i = 0; i < MRI; i++) acc[i] = 0ull;   // bits of (0.f, 0.f)

    const unsigned long long* xp = reinterpret_cast<const unsigned long long*>(x + col);
#pragma unroll 2
    for (int t = 0; t < TD; t++) {
        unsigned long long x2 = xp[(long)t * (SCOL / 2)];
#pragma unroll
        for (int mri = 0; mri < MRI; mri++) {
            fma2(acc[mri], x2, F2[(mri << 6) + t]);
        }
    }
#pragma unroll
    for (int mri = 0; mri < MRI; mri++) {
        *reinterpret_cast<unsigned long long*>(&g_Xft[(long)mri * SCOL + col]) = acc[mri];
    }
}

// =====================================================================
// Kernel 2: per-mode complex channel mix.
//   YR[p][o] = sum_c XR[p][c]*WR[c][o] - XI[p][c]*WI[c][o]
//   YI[p][o] = sum_c XR[p][c]*WI[c][o] + XI[p][c]*WR[c][o]
// grid = (PD/32, 16 modes), 256 threads. Dynamic smem 96KB:
//   W2a[c][o]=(WR,WI), W2b[c][o]=(-WI,WR), XR2/XI2 pre-broadcast-packed.
// Warp w handles pixels 4w..4w+3; lane l handles outputs 2l, 2l+1.
// Accumulator packs (YR, YI) per output.
// =====================================================================
__global__ void __launch_bounds__(256) k2_mix(const float* __restrict__ w) {
    extern __shared__ __align__(16) char smem[];
    float2*             W2a = reinterpret_cast<float2*>(smem);                      // 32 KB
    float2*             W2b = reinterpret_cast<float2*>(smem + 32768);              // 32 KB
    unsigned long long* XR2 = reinterpret_cast<unsigned long long*>(smem + 65536);  // 16 KB
    unsigned long long* XI2 = reinterpret_cast<unsigned long long*>(smem + 81920);  // 16 KB

    const int m   = blockIdx.y;
    const int p0  = blockIdx.x * 32;
    const int tid = threadIdx.x;

    // Load W_m: weights layout [c][o][m][2]
    for (int idx = tid; idx < CIN * COUT; idx += 256) {
        float2 wv = *reinterpret_cast<const float2*>(w + ((long)idx * MODES + m) * 2);
        W2a[idx] = wv;
        W2b[idx] = make_float2(-wv.y, wv.x);
    }
    // Load Xft tile for 32 pixels, pre-pack broadcast pairs
    const long rR = (long)(2 * m) * SCOL;
    const long rI = (long)(2 * m + 1) * SCOL;
    for (int idx = tid; idx < 32 * CIN; idx += 256) {
        long j = (long)p0 * CIN + idx;   // contiguous 32*64 block
        float xr = g_Xft[rR + j];
        float xi = g_Xft[rI + j];
        XR2[idx] = pack2(xr, xr);
        XI2[idx] = pack2(xi, xi);
    }
    __syncthreads();

    const int lane = tid & 31;
    const int wrp  = tid >> 5;

    unsigned long long a0[4], a1[4];
#pragma unroll
    for (int pit = 0; pit < 4; pit++) { a0[pit] = 0ull; a1[pit] = 0ull; }

#pragma unroll 4
    for (int c = 0; c < CIN; c++) {
        // lane's two outputs: contiguous 16B -> conflict-free LDS.128 across warp
        ulonglong2 wa = *reinterpret_cast<const ulonglong2*>(&W2a[(c << 6) + (lane << 1)]);
        ulonglong2 wb = *reinterpret_cast<const ulonglong2*>(&W2b[(c << 6) + (lane << 1)]);
#pragma unroll
        for (int pit = 0; pit < 4; pit++) {
            int pl = (wrp << 2) + pit;
            unsigned long long xr2 = XR2[(pl << 6) + c];   // broadcast
            unsigned long long xi2 = XI2[(pl << 6) + c];   // broadcast
            fma2(a0[pit], xr2, wa.x);
            fma2(a0[pit], xi2, wb.x);
            fma2(a1[pit], xr2, wa.y);
            fma2(a1[pit], xi2, wb.y);
        }
    }

#pragma unroll
    for (int pit = 0; pit < 4; pit++) {
        int pl = (wrp << 2) + pit;
        float yr0, yi0, yr1, yi1;
        unpack2(a0[pit], yr0, yi0);
        unpack2(a1[pit], yr1, yi1);
        long base = (long)(p0 + pl) * COUT + (lane << 1);
        *reinterpret_cast<float2*>(&g_Y[rR + base]) = make_float2(yr0, yr1);
        *reinterpret_cast<float2*>(&g_Y[rI + base]) = make_float2(yi0, yi1);
    }
}

// =====================================================================
// Kernel 3: truncated inverse real DFT (irfft with zero-padded modes).
//   out[t][p][o] = (1/64) * [ YR[0] + sum_{m=1..15} 2*(YR[m] cos - YI[m] sin) ]
//   G[t][2m]   =  alpha_m * cos(2*pi*m*t/64)/64   (alpha_0 = 1, else 2)
//   G[t][2m+1] = -alpha_m * sin(2*pi*m*t/64)/64   (== 0 for m=0: matches
//                irfft ignoring Im of the DC bin)
// =====================================================================
__global__ void __launch_bounds__(256) k3_irfft(float* __restrict__ out) {
    __shared__ unsigned long long G2[TD * MRI];   // [t][mri]
    const int tid = threadIdx.x;
    for (int idx = tid; idx < TD * MRI; idx += 256) {
        int t   = idx >> 5;
        int mri = idx & 31;
        int m   = mri >> 1;
        float ang = (float)((m * t) & 63) * TWO_PI_OVER_64;
        float s, c;
        sincosf(ang, &s, &c);
        float alpha = ((m == 0) ? 1.0f : 2.0f) * (1.0f / 64.0f);
        float v = (mri & 1) ? (-alpha * s) : (alpha * c);
        G2[idx] = pack2(v, v);
    }
    __syncthreads();

    const long col = ((long)blockIdx.x * 256 + tid) * 2;
    unsigned long long y2[MRI];
#pragma unroll
    for (int mri = 0; mri < MRI; mri++) {
        y2[mri] = *reinterpret_cast<const unsigned long long*>(&g_Y[(long)mri * SCOL + col]);
    }
    unsigned long long* op = reinterpret_cast<unsigned long long*>(out + col);
#pragma unroll 2
    for (int t = 0; t < TD; t++) {
        unsigned long long acc = 0ull;
#pragma unroll
        for (int mri = 0; mri < MRI; mri++) {
            fma2(acc, y2[mri], G2[(t << 5) + mri]);
        }
        op[(long)t * (SCOL / 2)] = acc;
    }
}

// =====================================================================
extern "C" void kernel_launch(void* const* d_in, const int* in_sizes, int n_in,
                              void* d_out, int out_size) {
    const float* x  = (const float*)d_in[0];   // [64][1024][16][64] f32
    const float* w  = (const float*)d_in[1];   // [64][64][16][2] f32
    float* out      = (float*)d_out;           // [64][1024][16][64] f32

    (void)in_sizes; (void)n_in; (void)out_size;

    cudaFuncSetAttribute(k2_mix, cudaFuncAttributeMaxDynamicSharedMemorySize, 98304);

    k1_rfft<<<2048, 256>>>(x);
    k2_mix<<<dim3(PD / 32, MODES), 256, 98304>>>(w);
    k3_irfft<<<2048, 256>>>(out);
}

// round 2
// speedup vs baseline: 1.0022x; 1.0022x over previous
#include <cuda_runtime.h>

// Problem constants
#define TD     64          // time dim
#define MODES  16
#define MRI    32          // 2*MODES (re/im interleaved rows)
#define CIN    64
#define COUT   64
#define PD     16384       // N*D = 1024*16 pixels
#define SCOL   1048576     // PD*64  (columns per time row, also per-mri row length)

// Scratch (module-load allocated, no cudaMalloc)
__device__ float g_Xft[33554432];   // [mri][p*64+c]  = 32 * 1048576 floats (128 MB)
__device__ float g_Y  [33554432];   // [mri][p*64+o]

#define TWO_PI_OVER_64 0.09817477042468103870f

// ---------- packed f32x2 helpers ----------
__device__ __forceinline__ unsigned long long pack2(float a, float b) {
    unsigned long long r;
    asm("mov.b64 %0, {%1, %2};" : "=l"(r) : "f"(a), "f"(b));
    return r;
}
__device__ __forceinline__ void unpack2(unsigned long long v, float &lo, float &hi) {
    asm("mov.b64 {%0, %1}, %2;" : "=f"(lo), "=f"(hi) : "l"(v));
}
__device__ __forceinline__ void fma2(unsigned long long &d, unsigned long long a, unsigned long long b) {
    asm("fma.rn.f32x2 %0, %1, %2, %0;" : "+l"(d) : "l"(a), "l"(b));
}

// =====================================================================
// Kernel 1: truncated real DFT along t.
//   Xft[2m  ][p][c] =  sum_t x[t][p][c] * cos(2*pi*m*t/64)
//   Xft[2m+1][p][c] = -sum_t x[t][p][c] * sin(2*pi*m*t/64)
// Each thread owns 2 adjacent columns (f32x2). 2048 blocks * 256 thr.
// =====================================================================
__global__ void __launch_bounds__(256) k1_rfft(const float* __restrict__ x) {
    __shared__ unsigned long long F2[MRI * TD];   // packed (f,f), [mri][t]
    const int tid = threadIdx.x;
    for (int idx = tid; idx < MRI * TD; idx += 256) {
        int mri = idx >> 6;
        int t   = idx & 63;
        int m   = mri >> 1;
        float ang = (float)((m * t) & 63) * TWO_PI_OVER_64;
        float s, c;
        sincosf(ang, &s, &c);
        float v = (mri & 1) ? -s : c;
        F2[idx] = pack2(v, v);
    }
    __syncthreads();

    const long col = ((long)blockIdx.x * 256 + tid) * 2;
    unsigned long long acc[MRI];
#pragma unroll
    for (int i = 0; i < MRI; i++) acc[i] = 0ull;   // bits of (0.f, 0.f)

    const unsigned long long* xp = reinterpret_cast<const unsigned long long*>(x + col);
#pragma unroll 2
    for (int t = 0; t < TD; t++) {
        unsigned long long x2 = xp[(long)t * (SCOL / 2)];
#pragma unroll
        for (int mri = 0; mri < MRI; mri++) {
            fma2(acc[mri], x2, F2[(mri << 6) + t]);
        }
    }
#pragma unroll
    for (int mri = 0; mri < MRI; mri++) {
        *reinterpret_cast<unsigned long long*>(&g_Xft[(long)mri * SCOL + col]) = acc[mri];
    }
}

// =====================================================================
// Kernel 2: per-mode complex channel mix.
//   YR[p][o] = sum_c XR[p][c]*WR[c][o] - XI[p][c]*WI[c][o]
//   YI[p][o] = sum_c XR[p][c]*WI[c][o] + XI[p][c]*WR[c][o]
// grid = (PD/32, 16 modes), 256 threads. Dynamic smem 96KB:
//   W2a[c][o]=(WR,WI), W2b[c][o]=(-WI,WR), XR2/XI2 pre-broadcast-packed.
// Warp w handles pixels 4w..4w+3; lane l handles outputs 2l, 2l+1.
// Accumulator packs (YR, YI) per output.
// =====================================================================
__global__ void __launch_bounds__(256) k2_mix(const float* __restrict__ w) {
    extern __shared__ __align__(16) char smem[];
    float2*             W2a = reinterpret_cast<float2*>(smem);                      // 32 KB
    float2*             W2b = reinterpret_cast<float2*>(smem + 32768);              // 32 KB
    unsigned long long* XR2 = reinterpret_cast<unsigned long long*>(smem + 65536);  // 16 KB
    unsigned long long* XI2 = reinterpret_cast<unsigned long long*>(smem + 81920);  // 16 KB

    const int m   = blockIdx.y;
    const int p0  = blockIdx.x * 32;
    const int tid = threadIdx.x;

    // Load W_m: weights layout [c][o][m][2]
    for (int idx = tid; idx < CIN * COUT; idx += 256) {
        float2 wv = *reinterpret_cast<const float2*>(w + ((long)idx * MODES + m) * 2);
        W2a[idx] = wv;
        W2b[idx] = make_float2(-wv.y, wv.x);
    }
    // Load Xft tile for 32 pixels, pre-pack broadcast pairs
    const long rR = (long)(2 * m) * SCOL;
    const long rI = (long)(2 * m + 1) * SCOL;
    for (int idx = tid; idx < 32 * CIN; idx += 256) {
        long j = (long)p0 * CIN + idx;   // contiguous 32*64 block
        float xr = g_Xft[rR + j];
        float xi = g_Xft[rI + j];
        XR2[idx] = pack2(xr, xr);
        XI2[idx] = pack2(xi, xi);
    }
    __syncthreads();

    const int lane = tid & 31;
    const int wrp  = tid >> 5;

    unsigned long long a0[4], a1[4];
#pragma unroll
    for (int pit = 0; pit < 4; pit++) { a0[pit] = 0ull; a1[pit] = 0ull; }

#pragma unroll 4
    for (int c = 0; c < CIN; c++) {
        // lane's two outputs: contiguous 16B -> conflict-free LDS.128 across warp
        ulonglong2 wa = *reinterpret_cast<const ulonglong2*>(&W2a[(c << 6) + (lane << 1)]);
        ulonglong2 wb = *reinterpret_cast<const ulonglong2*>(&W2b[(c << 6) + (lane << 1)]);
#pragma unroll
        for (int pit = 0; pit < 4; pit++) {
            int pl = (wrp << 2) + pit;
            unsigned long long xr2 = XR2[(pl << 6) + c];   // broadcast
            unsigned long long xi2 = XI2[(pl << 6) + c];   // broadcast
            fma2(a0[pit], xr2, wa.x);
            fma2(a0[pit], xi2, wb.x);
            fma2(a1[pit], xr2, wa.y);
            fma2(a1[pit], xi2, wb.y);
        }
    }

#pragma unroll
    for (int pit = 0; pit < 4; pit++) {
        int pl = (wrp << 2) + pit;
        float yr0, yi0, yr1, yi1;
        unpack2(a0[pit], yr0, yi0);
        unpack2(a1[pit], yr1, yi1);
        long base = (long)(p0 + pl) * COUT + (lane << 1);
        *reinterpret_cast<float2*>(&g_Y[rR + base]) = make_float2(yr0, yr1);
        *reinterpret_cast<float2*>(&g_Y[rI + base]) = make_float2(yi0, yi1);
    }
}

// =====================================================================
// Kernel 3: truncated inverse real DFT (irfft with zero-padded modes).
//   out[t][p][o] = (1/64) * [ YR[0] + sum_{m=1..15} 2*(YR[m] cos - YI[m] sin) ]
//   G[t][2m]   =  alpha_m * cos(2*pi*m*t/64)/64   (alpha_0 = 1, else 2)
//   G[t][2m+1] = -alpha_m * sin(2*pi*m*t/64)/64   (== 0 for m=0: matches
//                irfft ignoring Im of the DC bin)
// =====================================================================
__global__ void __launch_bounds__(256) k3_irfft(float* __restrict__ out) {
    __shared__ unsigned long long G2[TD * MRI];   // [t][mri]
    const int tid = threadIdx.x;
    for (int idx = tid; idx < TD * MRI; idx += 256) {
        int t   = idx >> 5;
        int mri = idx & 31;
        int m   = mri >> 1;
        float ang = (float)((m * t) & 63) * TWO_PI_OVER_64;
        float s, c;
        sincosf(ang, &s, &c);
        float alpha = ((m == 0) ? 1.0f : 2.0f) * (1.0f / 64.0f);
        float v = (mri & 1) ? (-alpha * s) : (alpha * c);
        G2[idx] = pack2(v, v);
    }
    __syncthreads();

    const long col = ((long)blockIdx.x * 256 + tid) * 2;
    unsigned long long y2[MRI];
#pragma unroll
    for (int mri = 0; mri < MRI; mri++) {
        y2[mri] = *reinterpret_cast<const unsigned long long*>(&g_Y[(long)mri * SCOL + col]);
    }
    unsigned long long* op = reinterpret_cast<unsigned long long*>(out + col);
#pragma unroll 2
    for (int t = 0; t < TD; t++) {
        unsigned long long acc = 0ull;
#pragma unroll
        for (int mri = 0; mri < MRI; mri++) {
            fma2(acc, y2[mri], G2[(t << 5) + mri]);
        }
        op[(long)t * (SCOL / 2)] = acc;
    }
}

// =====================================================================
extern "C" void kernel_launch(void* const* d_in, const int* in_sizes, int n_in,
                              void* d_out, int out_size) {
    const float* x  = (const float*)d_in[0];   // [64][1024][16][64] f32
    const float* w  = (const float*)d_in[1];   // [64][64][16][2] f32
    float* out      = (float*)d_out;           // [64][1024][16][64] f32

    (void)in_sizes; (void)n_in; (void)out_size;

    cudaFuncSetAttribute(k2_mix, cudaFuncAttributeMaxDynamicSharedMemorySize, 98304);

    k1_rfft<<<2048, 256>>>(x);
    k2_mix<<<dim3(PD / 32, MODES), 256, 98304>>>(w);
    k3_irfft<<<2048, 256>>>(out);
}

// round 3
// speedup vs baseline: 1.1481x; 1.1457x over previous
#include <cuda_runtime.h>

// Problem constants
#define TD     64
#define MODES  16
#define MRI    32          // 2*MODES
#define CIN    64
#define COUT   64
#define PD     16384       // N*D
#define SCOL   1048576     // PD*64 floats per time row
#define TILE_P 8
#define NBLK   (PD / TILE_P)   // 2048 CTAs

#define TWO_PI_OVER_64 0.09817477042468103870f

typedef unsigned long long u64;

// Packed, transposed weights: g_W[m][c2][o] = ( (WR[2c2][o],WR[2c2+1][o]), (WI[2c2][o],WI[2c2+1][o]) )
__device__ ulonglong2 g_W[MODES * 32 * 64];   // 512 KB

// ---------- packed f32x2 helpers ----------
__device__ __forceinline__ u64 pack2(float a, float b) {
    u64 r;
    asm("mov.b64 %0, {%1, %2};" : "=l"(r) : "f"(a), "f"(b));
    return r;
}
__device__ __forceinline__ void unpack2(u64 v, float &lo, float &hi) {
    asm("mov.b64 {%0, %1}, %2;" : "=f"(lo), "=f"(hi) : "l"(v));
}
__device__ __forceinline__ void fma2(u64 &d, u64 a, u64 b) {
    asm("fma.rn.f32x2 %0, %1, %2, %0;" : "+l"(d) : "l"(a), "l"(b));
}
__device__ __forceinline__ float hadd(u64 v) {
    float lo, hi;
    unpack2(v, lo, hi);
    return lo + hi;
}

// =====================================================================
// One-time weight repack: w[c][o][m][2]  ->  g_W[m][c2][o]
// =====================================================================
__global__ void __launch_bounds__(256) w_pack(const float* __restrict__ w) {
    int idx = blockIdx.x * 256 + threadIdx.x;     // 0 .. 32767
    int m  = idx >> 11;
    int c2 = (idx >> 6) & 31;
    int o  = idx & 63;
    int c0 = 2 * c2;
    const float* b0 = w + ((((c0    ) * 64 + o) * MODES + m) << 1);
    const float* b1 = w + ((((c0 + 1) * 64 + o) * MODES + m) << 1);
    ulonglong2 v;
    v.x = pack2(b0[0], b1[0]);   // (WR[2c2], WR[2c2+1])
    v.y = pack2(b0[1], b1[1]);   // (WI[2c2], WI[2c2+1])
    g_W[idx] = v;
}

// =====================================================================
// Fused spectral conv. 256 threads, 8 pixels per CTA, 224 KB smem.
// smem layout (bytes):
//   [0      , 16384 ) F2  [mri][t]   packed (f,f)    — stage1 DFT table
//   [16384  , 32768 ) G2  [t][mri]   packed (g,g)    — stage3 iDFT table
//   [32768  , 98304 ) Xft [mri][8p][64c] f32          (64 KB)
//   [98304  ,163840 ) Y   [mri][8p][64o] f32          (64 KB)
//   [163840 ,196608 ) W buf 0  [c2][o] ulonglong2     (32 KB)
//   [196608 ,229376 ) W buf 1                          (32 KB)
// =====================================================================
__global__ void __launch_bounds__(256, 1) fused_spectral(const float* __restrict__ x,
                                                         float* __restrict__ out) {
    extern __shared__ __align__(16) char smem[];
    u64*        F2  = reinterpret_cast<u64*>(smem);
    u64*        G2  = reinterpret_cast<u64*>(smem + 16384);
    float*      Xsm = reinterpret_cast<float*>(smem + 32768);
    float*      Ysm = reinterpret_cast<float*>(smem + 98304);
    ulonglong2* Wb0 = reinterpret_cast<ulonglong2*>(smem + 163840);
    ulonglong2* Wb1 = reinterpret_cast<ulonglong2*>(smem + 196608);

    const int tid = threadIdx.x;
    const int p0  = blockIdx.x * TILE_P;

    // ---- DFT tables ----
    for (int idx = tid; idx < MRI * TD; idx += 256) {      // F2[mri][t]
        int mri = idx >> 6, t = idx & 63, m = mri >> 1;
        float s, c;
        sincosf((float)((m * t) & 63) * TWO_PI_OVER_64, &s, &c);
        float v = (mri & 1) ? -s : c;
        F2[idx] = pack2(v, v);
    }
    for (int idx = tid; idx < TD * MRI; idx += 256) {      // G2[t][mri]
        int t = idx >> 5, mri = idx & 31, m = mri >> 1;
        float s, c;
        sincosf((float)((m * t) & 63) * TWO_PI_OVER_64, &s, &c);
        float alpha = ((m == 0) ? 1.0f : 2.0f) * (1.0f / 64.0f);
        float v = (mri & 1) ? (-alpha * s) : (alpha * c);
        G2[idx] = pack2(v, v);
    }

    // ---- prefetch W for mode 0 (overlaps with stage 1 gmem reads) ----
    ulonglong2 wreg[8];
#pragma unroll
    for (int k = 0; k < 8; k++) wreg[k] = g_W[tid + k * 256];

    __syncthreads();   // tables ready

    // =============== Stage 1: truncated rfft into smem ===============
    {
        const int p  = tid >> 5;         // pixel within tile (warp-uniform)
        const int cp = tid & 31;         // channel pair
        const u64* xp = reinterpret_cast<const u64*>(x) + (long)(p0 + p) * 32 + cp;

        u64 acc[MRI];
#pragma unroll
        for (int i = 0; i < MRI; i++) acc[i] = 0ull;

#pragma unroll 8
        for (int t = 0; t < TD; t++) {
            u64 xv = xp[(long)t * (SCOL / 2)];
#pragma unroll
            for (int mri = 0; mri < MRI; mri++)
                fma2(acc[mri], xv, F2[(mri << 6) + t]);
        }
        u64* Xs64 = reinterpret_cast<u64*>(Xsm);
#pragma unroll
        for (int mri = 0; mri < MRI; mri++)
            Xs64[(mri * TILE_P + p) * 32 + cp] = acc[mri];
        // publish happens at the sync inside the first mode iteration
    }

    // =============== Stage 2: per-mode complex channel mix ===============
    {
        const int o   = tid & 63;
        const int px0 = (tid >> 6) * 2;            // warp-uniform pixel pair
        const u64* Xs64 = reinterpret_cast<const u64*>(Xsm);

        for (int m = 0; m < MODES; m++) {
            ulonglong2* Wc = (m & 1) ? Wb1 : Wb0;
            // store this mode's W fragment (prefetched last iter / before stage1)
#pragma unroll
            for (int k = 0; k < 8; k++) Wc[tid + k * 256] = wreg[k];
            __syncthreads();   // W visible; iter 0 also publishes Xsm

            if (m < MODES - 1) {
#pragma unroll
                for (int k = 0; k < 8; k++)
                    wreg[k] = g_W[(m + 1) * 2048 + tid + k * 256];
            }

            const u64* xR = Xs64 + ((2 * m)     * TILE_P + px0) * 32;
            const u64* xI = Xs64 + ((2 * m + 1) * TILE_P + px0) * 32;

            u64 aRR0 = 0, aII0 = 0, aRI0 = 0, aIR0 = 0;
            u64 aRR1 = 0, aII1 = 0, aRI1 = 0, aIR1 = 0;

#pragma unroll 8
            for (int c2 = 0; c2 < 32; c2++) {
                ulonglong2 wv = Wc[(c2 << 6) + o];   // LDS.128, conflict-free
                u64 xr0 = xR[c2],      xi0 = xI[c2];        // warp broadcast
                u64 xr1 = xR[32 + c2], xi1 = xI[32 + c2];
                fma2(aRR0, xr0, wv.x); fma2(aII0, xi0, wv.y);
                fma2(aRI0, xr0, wv.y); fma2(aIR0, xi0, wv.x);
                fma2(aRR1, xr1, wv.x); fma2(aII1, xi1, wv.y);
                fma2(aRI1, xr1, wv.y); fma2(aIR1, xi1, wv.x);
            }

            // horizontal reduce + store Y
            float yr0 = hadd(aRR0) - hadd(aII0);
            float yi0 = hadd(aRI0) + hadd(aIR0);
            float yr1 = hadd(aRR1) - hadd(aII1);
            float yi1 = hadd(aRI1) + hadd(aIR1);
            Ysm[((2 * m)     * TILE_P + px0)     * 64 + o] = yr0;
            Ysm[((2 * m + 1) * TILE_P + px0)     * 64 + o] = yi0;
            Ysm[((2 * m)     * TILE_P + px0 + 1) * 64 + o] = yr1;
            Ysm[((2 * m + 1) * TILE_P + px0 + 1) * 64 + o] = yi1;
        }
    }
    __syncthreads();   // Y complete

    // =============== Stage 3: truncated irfft from smem ===============
    {
        const int p  = tid >> 5;
        const int op = tid & 31;
        const u64* Ys64 = reinterpret_cast<const u64*>(Ysm);

        u64 y2[MRI];
#pragma unroll
        for (int mri = 0; mri < MRI; mri++)
            y2[mri] = Ys64[(mri * TILE_P + p) * 32 + op];

        u64* outp = reinterpret_cast<u64*>(out) + (long)(p0 + p) * 32 + op;
#pragma unroll 4
        for (int t = 0; t < TD; t++) {
            u64 acc = 0ull;
#pragma unroll
            for (int mri = 0; mri < MRI; mri++)
                fma2(acc, y2[mri], G2[(t << 5) + mri]);
            outp[(long)t * (SCOL / 2)] = acc;
        }
    }
}

// =====================================================================
extern "C" void kernel_launch(void* const* d_in, const int* in_sizes, int n_in,
                              void* d_out, int out_size) {
    const float* x = (const float*)d_in[0];   // [64][1024][16][64] f32
    const float* w = (const float*)d_in[1];   // [64][64][16][2] f32
    float* out     = (float*)d_out;           // [64][1024][16][64] f32
    (void)in_sizes; (void)n_in; (void)out_size;

    cudaFuncSetAttribute(fused_spectral, cudaFuncAttributeMaxDynamicSharedMemorySize, 229376);

    w_pack<<<128, 256>>>(w);
    fused_spectral<<<NBLK, 256, 229376>>>(x, out);
}

// round 4
// speedup vs baseline: 1.1507x; 1.0022x over previous
#include <cuda_runtime.h>

// Problem constants
#define TD     64
#define MODES  16
#define MRI    32          // 2*MODES
#define CIN    64
#define COUT   64
#define PD     16384       // N*D
#define SCOL   1048576     // PD*64 floats per time row
#define TILE_P 8
#define NBLK   (PD / TILE_P)   // 2048 CTAs

#define TWO_PI_OVER_64 0.09817477042468103870f

typedef unsigned long long u64;

// Packed, transposed weights: g_W[m][c2][o] = ( (WR[2c2][o],WR[2c2+1][o]), (WI[2c2][o],WI[2c2+1][o]) )
__device__ ulonglong2 g_W[MODES * 32 * 64];   // 512 KB

// ---------- packed f32x2 helpers ----------
__device__ __forceinline__ u64 pack2(float a, float b) {
    u64 r;
    asm("mov.b64 %0, {%1, %2};" : "=l"(r) : "f"(a), "f"(b));
    return r;
}
__device__ __forceinline__ void unpack2(u64 v, float &lo, float &hi) {
    asm("mov.b64 {%0, %1}, %2;" : "=f"(lo), "=f"(hi) : "l"(v));
}
__device__ __forceinline__ void fma2(u64 &d, u64 a, u64 b) {
    asm("fma.rn.f32x2 %0, %1, %2, %0;" : "+l"(d) : "l"(a), "l"(b));
}
__device__ __forceinline__ float hadd(u64 v) {
    float lo, hi;
    unpack2(v, lo, hi);
    return lo + hi;
}

// =====================================================================
// One-time weight repack: w[c][o][m][2]  ->  g_W[m][c2][o]
// =====================================================================
__global__ void __launch_bounds__(256) w_pack(const float* __restrict__ w) {
    int idx = blockIdx.x * 256 + threadIdx.x;     // 0 .. 32767
    int m  = idx >> 11;
    int c2 = (idx >> 6) & 31;
    int o  = idx & 63;
    int c0 = 2 * c2;
    const float* b0 = w + ((((c0    ) * 64 + o) * MODES + m) << 1);
    const float* b1 = w + ((((c0 + 1) * 64 + o) * MODES + m) << 1);
    ulonglong2 v;
    v.x = pack2(b0[0], b1[0]);   // (WR[2c2], WR[2c2+1])
    v.y = pack2(b0[1], b1[1]);   // (WI[2c2], WI[2c2+1])
    g_W[idx] = v;
}

// =====================================================================
// Fused spectral conv. 256 threads, 8 pixels per CTA, 224 KB smem.
// smem layout (bytes):
//   [0      , 16384 ) F2  [mri][t]   packed (f,f)    — stage1 DFT table
//   [16384  , 32768 ) G2  [t][mri]   packed (g,g)    — stage3 iDFT table
//   [32768  , 98304 ) Xft [mri][8p][64c] f32          (64 KB)
//   [98304  ,163840 ) Y   [mri][8p][64o] f32          (64 KB)
//   [163840 ,196608 ) W buf 0  [c2][o] ulonglong2     (32 KB)
//   [196608 ,229376 ) W buf 1                          (32 KB)
// =====================================================================
__global__ void __launch_bounds__(256, 1) fused_spectral(const float* __restrict__ x,
                                                         float* __restrict__ out) {
    extern __shared__ __align__(16) char smem[];
    u64*        F2  = reinterpret_cast<u64*>(smem);
    u64*        G2  = reinterpret_cast<u64*>(smem + 16384);
    float*      Xsm = reinterpret_cast<float*>(smem + 32768);
    float*      Ysm = reinterpret_cast<float*>(smem + 98304);
    ulonglong2* Wb0 = reinterpret_cast<ulonglong2*>(smem + 163840);
    ulonglong2* Wb1 = reinterpret_cast<ulonglong2*>(smem + 196608);

    const int tid = threadIdx.x;
    const int p0  = blockIdx.x * TILE_P;

    // ---- DFT tables ----
    for (int idx = tid; idx < MRI * TD; idx += 256) {      // F2[mri][t]
        int mri = idx >> 6, t = idx & 63, m = mri >> 1;
        float s, c;
        sincosf((float)((m * t) & 63) * TWO_PI_OVER_64, &s, &c);
        float v = (mri & 1) ? -s : c;
        F2[idx] = pack2(v, v);
    }
    for (int idx = tid; idx < TD * MRI; idx += 256) {      // G2[t][mri]
        int t = idx >> 5, mri = idx & 31, m = mri >> 1;
        float s, c;
        sincosf((float)((m * t) & 63) * TWO_PI_OVER_64, &s, &c);
        float alpha = ((m == 0) ? 1.0f : 2.0f) * (1.0f / 64.0f);
        float v = (mri & 1) ? (-alpha * s) : (alpha * c);
        G2[idx] = pack2(v, v);
    }

    // ---- prefetch W for mode 0 (overlaps with stage 1 gmem reads) ----
    ulonglong2 wreg[8];
#pragma unroll
    for (int k = 0; k < 8; k++) wreg[k] = g_W[tid + k * 256];

    __syncthreads();   // tables ready

    // =============== Stage 1: truncated rfft into smem ===============
    {
        const int p  = tid >> 5;         // pixel within tile (warp-uniform)
        const int cp = tid & 31;         // channel pair
        const u64* xp = reinterpret_cast<const u64*>(x) + (long)(p0 + p) * 32 + cp;

        u64 acc[MRI];
#pragma unroll
        for (int i = 0; i < MRI; i++) acc[i] = 0ull;

#pragma unroll 8
        for (int t = 0; t < TD; t++) {
            u64 xv = xp[(long)t * (SCOL / 2)];
#pragma unroll
            for (int mri = 0; mri < MRI; mri++)
                fma2(acc[mri], xv, F2[(mri << 6) + t]);
        }
        u64* Xs64 = reinterpret_cast<u64*>(Xsm);
#pragma unroll
        for (int mri = 0; mri < MRI; mri++)
            Xs64[(mri * TILE_P + p) * 32 + cp] = acc[mri];
        // publish happens at the sync inside the first mode iteration
    }

    // =============== Stage 2: per-mode complex channel mix ===============
    {
        const int o   = tid & 63;
        const int px0 = (tid >> 6) * 2;            // warp-uniform pixel pair
        const u64* Xs64 = reinterpret_cast<const u64*>(Xsm);

        for (int m = 0; m < MODES; m++) {
            ulonglong2* Wc = (m & 1) ? Wb1 : Wb0;
            // store this mode's W fragment (prefetched last iter / before stage1)
#pragma unroll
            for (int k = 0; k < 8; k++) Wc[tid + k * 256] = wreg[k];
            __syncthreads();   // W visible; iter 0 also publishes Xsm

            if (m < MODES - 1) {
#pragma unroll
                for (int k = 0; k < 8; k++)
                    wreg[k] = g_W[(m + 1) * 2048 + tid + k * 256];
            }

            const u64* xR = Xs64 + ((2 * m)     * TILE_P + px0) * 32;
            const u64* xI = Xs64 + ((2 * m + 1) * TILE_P + px0) * 32;

            u64 aRR0 = 0, aII0 = 0, aRI0 = 0, aIR0 = 0;
            u64 aRR1 = 0, aII1 = 0, aRI1 = 0, aIR1 = 0;

#pragma unroll 8
            for (int c2 = 0; c2 < 32; c2++) {
                ulonglong2 wv = Wc[(c2 << 6) + o];   // LDS.128, conflict-free
                u64 xr0 = xR[c2],      xi0 = xI[c2];        // warp broadcast
                u64 xr1 = xR[32 + c2], xi1 = xI[32 + c2];
                fma2(aRR0, xr0, wv.x); fma2(aII0, xi0, wv.y);
                fma2(aRI0, xr0, wv.y); fma2(aIR0, xi0, wv.x);
                fma2(aRR1, xr1, wv.x); fma2(aII1, xi1, wv.y);
                fma2(aRI1, xr1, wv.y); fma2(aIR1, xi1, wv.x);
            }

            // horizontal reduce + store Y
            float yr0 = hadd(aRR0) - hadd(aII0);
            float yi0 = hadd(aRI0) + hadd(aIR0);
            float yr1 = hadd(aRR1) - hadd(aII1);
            float yi1 = hadd(aRI1) + hadd(aIR1);
            Ysm[((2 * m)     * TILE_P + px0)     * 64 + o] = yr0;
            Ysm[((2 * m + 1) * TILE_P + px0)     * 64 + o] = yi0;
            Ysm[((2 * m)     * TILE_P + px0 + 1) * 64 + o] = yr1;
            Ysm[((2 * m + 1) * TILE_P + px0 + 1) * 64 + o] = yi1;
        }
    }
    __syncthreads();   // Y complete

    // =============== Stage 3: truncated irfft from smem ===============
    {
        const int p  = tid >> 5;
        const int op = tid & 31;
        const u64* Ys64 = reinterpret_cast<const u64*>(Ysm);

        u64 y2[MRI];
#pragma unroll
        for (int mri = 0; mri < MRI; mri++)
            y2[mri] = Ys64[(mri * TILE_P + p) * 32 + op];

        u64* outp = reinterpret_cast<u64*>(out) + (long)(p0 + p) * 32 + op;
#pragma unroll 4
        for (int t = 0; t < TD; t++) {
            u64 acc = 0ull;
#pragma unroll
            for (int mri = 0; mri < MRI; mri++)
                fma2(acc, y2[mri], G2[(t << 5) + mri]);
            outp[(long)t * (SCOL / 2)] = acc;
        }
    }
}

// =====================================================================
extern "C" void kernel_launch(void* const* d_in, const int* in_sizes, int n_in,
                              void* d_out, int out_size) {
    const float* x = (const float*)d_in[0];   // [64][1024][16][64] f32
    const float* w = (const float*)d_in[1];   // [64][64][16][2] f32
    float* out     = (float*)d_out;           // [64][1024][16][64] f32
    (void)in_sizes; (void)n_in; (void)out_size;

    cudaFuncSetAttribute(fused_spectral, cudaFuncAttributeMaxDynamicSharedMemorySize, 229376);

    w_pack<<<128, 256>>>(w);
    fused_spectral<<<NBLK, 256, 229376>>>(x, out);
}